// round 8
// baseline (speedup 1.0000x reference)
#include <cuda_runtime.h>
#include <cuda_bf16.h>
#include <limits.h>

// SHSidechainDecoder: NX=41 cube, voxel 0.3, r_max 6.0, min_sep 3, K=4.
#define GRIDG   68921            // 41^3
#define NXC     41
#define NCOL    1681             // 41*41 (i,j) columns; k contiguous in column
#define KPEAKS  4
#define NEGV    (-1.0e9f)
#define VALID_T (-1.0e8f)
#define THREADS 1024
#define NWARPS  (THREADS / 32)   // 32

// Static per-replay table: k0 | (cnt<<8) per (i,j) column.
__device__ int g_kc[NCOL];

// Sphere-mask table build. The grid is a product grid:
//   x_i = grid_xyz[3*(i*1681)+0], y_j = grid_xyz[3*(j*41)+1], z_k = grid_xyz[3*k+2]
// numpy fp32 predicate: sqrt((x*x + y*y) + z*z) <= 6.0 (pairwise add order,
// no FMA). z_{20+m} and z_{20-m} square to identical bits and the predicate
// is monotone non-increasing in m, so the inside-set per column is
// |k-20| <= m_max: found by a 5-step binary search. Bit-exact vs numpy.
__global__ void tables_kernel(const float* __restrict__ grid_xyz) {
    __shared__ float s_zz[21];
    const int t = threadIdx.x;
    if (t < 21) {
        float z = grid_xyz[3 * (20 + t) + 2];      // z_{20+m}, m = t
        s_zz[t] = __fmul_rn(z, z);
    }
    __syncthreads();

    int c = blockIdx.x * blockDim.x + t;
    if (c >= NCOL) return;
    int i = c / NXC;
    int j = c - i * NXC;
    float x = grid_xyz[3 * (i * NCOL) + 0];
    float y = grid_xyz[3 * (j * NXC) + 1];
    float sxy = __fadd_rn(__fmul_rn(x, x), __fmul_rn(y, y));

    int k0 = 0, cnt = 0;
    if (__fsqrt_rn(__fadd_rn(sxy, s_zz[0])) <= 6.0f) {
        int lo = 0, hi = 20;
        while (lo < hi) {                          // largest m with pred(m)
            int mid = (lo + hi + 1) >> 1;
            if (__fsqrt_rn(__fadd_rn(sxy, s_zz[mid])) <= 6.0f) lo = mid;
            else hi = mid - 1;
        }
        k0  = 20 - lo;
        cnt = 2 * lo + 1;
    }
    g_kc[c] = k0 | (cnt << 8);
}

// Comparator: max value, min global-index tie-break (jnp.argmax semantics).
__device__ __forceinline__ void amax2(float& bv, int& bg, float v, int g) {
    if (v > bv || (v == bv && g < bg)) { bv = v; bg = g; }
}

// One block per (bn,c) slice, ~20KB SMEM -> 2 blocks/SM. One masked DRAM pass
// reduces each column to (max, arg-g) via warp shuffles; selection per peak is
// an argmax over 1681 column maxes; suppression repair re-reads the 7x7
// affected columns from L2, rewriting cells inside any prior valid peak's
// Chebyshev box to NEG before re-reducing.
__global__ __launch_bounds__(THREADS) void peaks_kernel(
    const float* __restrict__ density,
    const float* __restrict__ grid_xyz,
    const float* __restrict__ Rmats,
    const float* __restrict__ tpos,
    const float* __restrict__ node_mask,
    float* __restrict__ out,
    int NC, int C)
{
    __shared__ int   s_kc[NCOL];
    __shared__ float s_colmax[NCOL];
    __shared__ int   s_colpos[NCOL];          // global grid index g of col max
    __shared__ float s_wval[NWARPS];
    __shared__ int   s_widx[NWARPS];
    __shared__ float s_pk_score[KPEAKS];
    __shared__ int   s_pk_g[KPEAKS];
    __shared__ int   s_pk_i[KPEAKS], s_pk_j[KPEAKS], s_pk_k[KPEAKS];
    __shared__ int   s_pk_valid[KPEAKS];

    const int tid  = threadIdx.x;
    const int lane = tid & 31;
    const int wid  = tid >> 5;
    const int nc   = blockIdx.x;
    const float* __restrict__ slice = density + (size_t)nc * GRIDG;

    for (int i = tid; i < NCOL; i += THREADS) s_kc[i] = g_kc[i];
    __syncthreads();

    // ---- Pass 1: masked DRAM read, per-column warp argmax ----
    // Process 4 columns per warp iteration: batch the (predicated) loads of
    // all 4 columns first for MLP, then reduce.
#pragma unroll 2
    for (int base = wid; base < NCOL; base += NWARPS * 4) {
        float v0[4], v1[4];
        int   kcs[4];
#pragma unroll
        for (int u = 0; u < 4; ++u) {
            int col = base + u * NWARPS;
            float a = -3.0e9f, b = -3.0e9f;
            int kc = 0;
            if (col < NCOL) {
                kc = s_kc[col];
                int cnt = kc >> 8;
                const float* p = slice + col * NXC + (kc & 0xff);
                if (lane < cnt)      a = __ldg(p + lane);
                if (lane + 32 < cnt) b = __ldg(p + lane + 32);
            }
            v0[u] = a; v1[u] = b; kcs[u] = kc;
        }
#pragma unroll
        for (int u = 0; u < 4; ++u) {
            int col = base + u * NWARPS;
            if (col >= NCOL) continue;
            int kc  = kcs[u];
            int cnt = kc >> 8;
            int gb  = col * NXC + (kc & 0xff);
            float bv = -3.0e9f; int bg = INT_MAX;
            if (lane < cnt)      amax2(bv, bg, v0[u], gb + lane);
            if (lane + 32 < cnt) amax2(bv, bg, v1[u], gb + lane + 32);
#pragma unroll
            for (int off = 16; off > 0; off >>= 1) {
                float v2 = __shfl_down_sync(0xffffffffu, bv, off);
                int   g2 = __shfl_down_sync(0xffffffffu, bg, off);
                amax2(bv, bg, v2, g2);
            }
            if (lane == 0) { s_colmax[col] = bv; s_colpos[col] = bg; }
        }
    }
    __syncthreads();

    for (int kp = 0; kp < KPEAKS; ++kp) {
        // ---- Selection: argmax over 1681 column maxes ----
        float bv = -3.0e9f; int bg = INT_MAX;
        for (int c = tid; c < NCOL; c += THREADS)
            amax2(bv, bg, s_colmax[c], s_colpos[c]);
#pragma unroll
        for (int off = 16; off > 0; off >>= 1) {
            float v2 = __shfl_down_sync(0xffffffffu, bv, off);
            int   g2 = __shfl_down_sync(0xffffffffu, bg, off);
            amax2(bv, bg, v2, g2);
        }
        if (lane == 0) { s_wval[wid] = bv; s_widx[wid] = bg; }
        __syncthreads();
        if (tid < 32) {
            float v = s_wval[tid];
            int   g = s_widx[tid];
#pragma unroll
            for (int off = 16; off > 0; off >>= 1) {
                float v2 = __shfl_down_sync(0xffffffffu, v, off);
                int   g2 = __shfl_down_sync(0xffffffffu, g, off);
                amax2(v, g, v2, g2);
            }
            if (tid == 0) {
                int valid = (v > VALID_T) ? 1 : 0;
                s_pk_score[kp] = v;
                s_pk_valid[kp] = valid;
                int gg = valid ? g : 0;
                int ii = gg / NCOL;
                int rem = gg - ii * NCOL;
                int jj = rem / NXC;
                s_pk_i[kp] = ii;
                s_pk_j[kp] = jj;
                s_pk_k[kp] = rem - jj * NXC;
                s_pk_g[kp] = gg;
            }
        }
        __syncthreads();

        // ---- Repair: recompute the 7x7 columns around the new peak from
        //      L2, with cells inside ANY prior valid peak's box set to NEG ----
        if (kp < KPEAKS - 1 && s_pk_valid[kp]) {
            const int pi = s_pk_i[kp], pj = s_pk_j[kp];
            for (int cand = wid; cand < 49; cand += NWARPS) {
                int dj = cand / 7, di = cand - dj * 7;
                int i = pi + di - 3;
                int j = pj + dj - 3;
                if ((unsigned)i >= NXC || (unsigned)j >= NXC) continue;
                int col = i * NXC + j;
                int kc  = s_kc[col];
                int cnt = kc >> 8;
                int k0  = kc & 0xff;
                int gb  = col * NXC + k0;
                float cbv = -3.0e9f; int cbg = INT_MAX;
#pragma unroll
                for (int r = 0; r < 2; ++r) {
                    int o = lane + r * 32;
                    if (o < cnt) {
                        int k = k0 + o;
                        float v = __ldg(slice + gb + o);
                        for (int p = 0; p <= kp; ++p) {
                            if (s_pk_valid[p] &&
                                abs(i - s_pk_i[p]) <= 3 &&
                                abs(j - s_pk_j[p]) <= 3 &&
                                abs(k - s_pk_k[p]) <= 3)
                                v = NEGV;          // reference rewrite value
                        }
                        amax2(cbv, cbg, v, gb + o);
                    }
                }
#pragma unroll
                for (int off = 16; off > 0; off >>= 1) {
                    float v2 = __shfl_down_sync(0xffffffffu, cbv, off);
                    int   g2 = __shfl_down_sync(0xffffffffu, cbg, off);
                    amax2(cbv, cbg, v2, g2);
                }
                if (lane == 0) { s_colmax[col] = cbv; s_colpos[col] = cbg; }
            }
            __syncthreads();
        }
    }

    // ---- Epilogue: threads 0..3 each write one peak ----
    if (tid < KPEAKS) {
        const int kk = tid;
        const int n  = nc / C;
        const float nm = node_mask[n];
        const int valid = s_pk_valid[kk];

        float x = 0.f, y = 0.f, z = 0.f;
        if (valid) {
            int ix = s_pk_g[kk];
            x = grid_xyz[3 * ix + 0];
            y = grid_xyz[3 * ix + 1];
            z = grid_xyz[3 * ix + 2];
        }
        const float* R = Rmats + (size_t)n * 9;
        const float* t = tpos  + (size_t)n * 3;
        float gx = R[0] * x + R[1] * y + R[2] * z + t[0];
        float gy = R[3] * x + R[4] * y + R[5] * z + t[1];
        float gz = R[6] * x + R[7] * y + R[8] * z + t[2];

        float score = valid ? s_pk_score[kk] : NEGV;

        const int NCK   = NC * KPEAKS;
        const int base3 = (nc * KPEAKS + kk) * 3;
        out[base3 + 0] = x * nm;                       // coords_local
        out[base3 + 1] = y * nm;
        out[base3 + 2] = z * nm;
        out[NCK * 3 + base3 + 0] = gx * nm;            // coords_global
        out[NCK * 3 + base3 + 1] = gy * nm;
        out[NCK * 3 + base3 + 2] = gz * nm;
        out[NCK * 6 + nc * KPEAKS + kk] = score * nm;  // scores
        out[NCK * 7 + nc * KPEAKS + kk] = (valid && nm != 0.0f) ? 1.0f : 0.0f; // mask
    }
}

extern "C" void kernel_launch(void* const* d_in, const int* in_sizes, int n_in,
                              void* d_out, int out_size) {
    // Inputs: density, grid_xyz, sphere_mask, coords_int, Rmats, tpos, node_mask
    const float* density   = (const float*)d_in[0];
    const float* grid_xyz  = (const float*)d_in[1];
    const float* Rmats     = (const float*)d_in[4];
    const float* tpos      = (const float*)d_in[5];
    const float* node_mask = (const float*)d_in[6];
    float* out = (float*)d_out;

    int BN = in_sizes[6];                // B*N
    int NC = in_sizes[0] / GRIDG;        // B*N*C slices
    int C  = NC / BN;

    tables_kernel<<<(NCOL + 255) / 256, 256>>>(grid_xyz);
    peaks_kernel<<<NC, THREADS>>>(density, grid_xyz, Rmats, tpos,
                                  node_mask, out, NC, C);
}